// round 8
// baseline (speedup 1.0000x reference)
#include <cuda_runtime.h>
#include <cuda_fp16.h>
#include <cstdint>

#define DIM    256
#define NEMB   8192
#define NROW   16384
#define DECAYF 0.99f
#define OMDF   0.01f
#define EPSF   1e-5f
#define MARGIN 1.0f

// A: 128 rows x 512B (256 fp16 hi), padded stride 528B
#define AST    528
#define AREG   (128 * AST)          // 67584
#define BST    144                  // B slice row: 64 fp16 = 128B + 16 pad
#define BBUF   (256 * BST)          // 36864 (256 codes per stage)
#define SM_A   0
#define SM_B   AREG                 // 67584
#define SM_RB  (SM_B + 3 * BBUF)    // 178176 rowbest int[128]
#define SM_CNT (SM_RB + 512)        // 178688 cnt int[128]
#define SM_CD  (SM_CNT + 512)       // 179200 cand int[128*32]
#define SMEM_SZ (SM_CD + 128 * 32 * 4)  // 195584
#define NSTG   128                  // 32 chunks (256 codes) x 4 k-stages

// ---- scratch (device globals: no allocations allowed) ----
__device__ float g_enorm[NEMB];
__device__ float g_embT[NEMB * DIM];          // [j][d] fp32 for rescore + gather
__device__ float g_esum[NEMB * DIM];          // [j][d] segment sums
__device__ int   g_argmin[NROW];
__device__ float g_n;
__device__ __half g_zsH[(size_t)NROW * DIM];  // [m][d] fp16
__device__ __half g_esH[(size_t)NEMB * DIM];  // [j][d] fp16

// ================= helpers =================
__device__ __forceinline__ uint32_t smem_u32(const void* p) {
    uint32_t a;
    asm("{ .reg .u64 t; cvta.to.shared.u64 t, %1; cvt.u32.u64 %0, t; }" : "=r"(a) : "l"(p));
    return a;
}
__device__ __forceinline__ void cpa16(uint32_t dst, const void* src) {
    asm volatile("cp.async.cg.shared.global [%0], [%1], 16;" :: "r"(dst), "l"(src));
}
__device__ __forceinline__ void ldm4(uint32_t (&r)[4], uint32_t addr) {
    asm volatile("ldmatrix.sync.aligned.m8n8.x4.shared.b16 {%0,%1,%2,%3}, [%4];"
                 : "=r"(r[0]), "=r"(r[1]), "=r"(r[2]), "=r"(r[3]) : "r"(addr));
}
__device__ __forceinline__ void mma16816(float (&d)[4], const uint32_t (&a)[4],
                                         uint32_t b0, uint32_t b1) {
    asm volatile(
        "mma.sync.aligned.m16n8k16.row.col.f32.f16.f16.f32 "
        "{%0,%1,%2,%3},{%4,%5,%6,%7},{%8,%9},{%0,%1,%2,%3};"
        : "+f"(d[0]), "+f"(d[1]), "+f"(d[2]), "+f"(d[3])
        : "r"(a[0]), "r"(a[1]), "r"(a[2]), "r"(a[3]), "r"(b0), "r"(b1));
}

// ================= prep: z -> fp16 =================
__global__ void k_prep_z(const float* __restrict__ z) {
    int i = blockIdx.x * blockDim.x + threadIdx.x;
    if (i < NROW * DIM) g_zsH[i] = __float2half(z[i]);
}

// ================= prep: emb -> fp16 + embT + esum=0 (tiled transpose) ====
__global__ void k_prep_e(const float* __restrict__ emb) {
    __shared__ float t[32][33];
    int j0 = blockIdx.x * 32, d0 = blockIdx.y * 32;
    for (int r = threadIdx.y; r < 32; r += 8)
        t[r][threadIdx.x] = emb[(size_t)(d0 + r) * NEMB + j0 + threadIdx.x];
    __syncthreads();
    for (int r = threadIdx.y; r < 32; r += 8) {
        int j = j0 + r, d = d0 + threadIdx.x;
        float x = t[threadIdx.x][r];
        g_esH[(size_t)j * DIM + d] = __float2half(x);
        g_embT[j * DIM + d] = x;
        g_esum[j * DIM + d] = 0.0f;
    }
}

// ================= code norms + init cs + zero diff =================
__global__ void k_enorm(const float* __restrict__ emb, const float* __restrict__ cs,
                        float* __restrict__ o_cs, float* __restrict__ o_diff) {
    int j = blockIdx.x * blockDim.x + threadIdx.x;
    if (j < NEMB) {
        float s = 0.0f;
#pragma unroll 8
        for (int d = 0; d < DIM; ++d) {
            float v = emb[(size_t)d * NEMB + j];
            s = fmaf(v, v, s);
        }
        g_enorm[j] = s;
        o_cs[j] = DECAYF * cs[j];
        if (j == 0) *o_diff = 0.0f;
    }
}

// ================= main: fp16 approx GEMM + threshold candidates + rescore ======
__device__ __forceinline__ void load_B(int t, int slot, int tid, uint32_t sb) {
    const int n0 = (t >> 2) << 8;       // chunk * 256 codes
    const int scol = (t & 3) << 6;      // k-slice * 64
    const char* ea = (const char*)g_esH;
#pragma unroll
    for (int r = 0; r < 4; ++r) {
        int i = tid + (r << 9);
        int c = i & 7, row = i >> 3;    // 256 rows x 8 chunks of 16B
        cpa16(sb + SM_B + slot * BBUF + row * BST + c * 16,
              ea + (((size_t)(n0 + row) << 8) + scol) * 2 + c * 16);
    }
}

__global__ __launch_bounds__(512, 1)
void k_argmin_mma(const float* __restrict__ z, float* __restrict__ o_ind) {
    extern __shared__ char smm[];
    uint32_t sb = smem_u32(smm);
    const int tid = threadIdx.x;
    const int lane = tid & 31;
    const int warp = tid >> 5;
    const int warpM = warp >> 2;        // 0..3 (32 rows each)
    const int warpN = warp & 3;         // 0..3 (64 codes each)
    const int m0 = blockIdx.x * 128;

    int* rowbest = (int*)(smm + SM_RB);
    int* cnt     = (int*)(smm + SM_CNT);
    int* cand    = (int*)(smm + SM_CD);
    if (tid < 128) { rowbest[tid] = 0x7f800000; cnt[tid] = 0; }

    // per-lane ldmatrix offsets
    const int q = lane >> 3, rq = lane & 7;
    const int lrow = (q & 1) * 8 + rq;
    const int lbyte = (q >> 1) * 16;
    const uint32_t a_lane = (uint32_t)lrow * AST + lbyte;
    const uint32_t b_lane = (uint32_t)lrow * BST + lbyte;

    // prologue: A + stage0 -> group0; stage1 -> group1
    const char* za = (const char*)g_zsH;
#pragma unroll
    for (int r = 0; r < 8; ++r) {
        int i = tid + (r << 9);
        int c = i & 31, row = i >> 5;
        cpa16(sb + SM_A + row * AST + c * 16,
              za + ((size_t)(m0 + row) << 8) * 2 + c * 16);
    }
    load_B(0, 0, tid, sb);
    asm volatile("cp.async.commit_group;" ::: "memory");
    load_B(1, 1, tid, sb);
    asm volatile("cp.async.commit_group;" ::: "memory");

    const int lq = lane >> 2;
    const int ln = (lane & 3) * 2;
    int rowix[4];
#pragma unroll
    for (int sl = 0; sl < 4; ++sl)
        rowix[sl] = warpM * 32 + (sl >> 1) * 16 + (sl & 1) * 8 + lq;

    float acc[2][8][4];
    int cur = 0, nxt = 2;

    for (int t = 0; t < NSTG; ++t) {
        const int s = t & 3;
        if (s == 0) {
#pragma unroll
            for (int mt = 0; mt < 2; ++mt)
#pragma unroll
                for (int nt = 0; nt < 8; ++nt)
#pragma unroll
                    for (int x = 0; x < 4; ++x) acc[mt][nt][x] = 0.0f;
        }

        if (t == NSTG - 1) {
            asm volatile("cp.async.wait_group 0;" ::: "memory");
        } else {
            asm volatile("cp.async.wait_group 1;" ::: "memory");
        }
        __syncthreads();

        if (t + 2 < NSTG) {
            load_B(t + 2, nxt, tid, sb);
            asm volatile("cp.async.commit_group;" ::: "memory");
        }

        const uint32_t Bb = sb + SM_B + cur * BBUF + (warpN * 64) * BST + b_lane;
        const uint32_t Ab0 = sb + SM_A + (warpM * 32) * AST + s * 128 + a_lane;
#pragma unroll
        for (int kk = 0; kk < 4; ++kk) {
            uint32_t b[4][4];
#pragma unroll
            for (int g = 0; g < 4; ++g)
                ldm4(b[g], Bb + g * 16 * BST + kk * 32);
            uint32_t a0[4], a1[4];
            ldm4(a0, Ab0 + kk * 32);
            ldm4(a1, Ab0 + 16 * AST + kk * 32);
#pragma unroll
            for (int nt = 0; nt < 8; ++nt) {
                uint32_t bb0 = b[nt >> 1][nt & 1];
                uint32_t bb1 = b[nt >> 1][(nt & 1) + 2];
                mma16816(acc[0][nt], a0, bb0, bb1);
                mma16816(acc[1][nt], a1, bb0, bb1);
            }
        }

        if (s == 3) {   // chunk done
            const int n0 = (t >> 2) << 8;
            const int cbase = n0 + warpN * 64 + ln;
            float smin[4] = {3.4e38f, 3.4e38f, 3.4e38f, 3.4e38f};
#pragma unroll
            for (int nt = 0; nt < 8; ++nt) {
#pragma unroll
                for (int jj = 0; jj < 2; ++jj) {
                    const float en = __ldg(&g_enorm[cbase + nt * 8 + jj]);
#pragma unroll
                    for (int mt = 0; mt < 2; ++mt)
#pragma unroll
                        for (int h = 0; h < 2; ++h) {
                            float d = fmaf(-2.0f, acc[mt][nt][h * 2 + jj], en);
                            smin[mt * 2 + h] = fminf(smin[mt * 2 + h], d);
                        }
                }
            }
            if (t == 3) {
                // seed rowbest from chunk 0, then append chunk-0 candidates
#pragma unroll
                for (int sl = 0; sl < 4; ++sl)
                    atomicMin(&rowbest[rowix[sl]], __float_as_int(smin[sl]));
                __syncthreads();
#pragma unroll
                for (int sl = 0; sl < 4; ++sl) {
                    float thr = __int_as_float(rowbest[rowix[sl]]) + MARGIN;
#pragma unroll
                    for (int nt = 0; nt < 8; ++nt)
#pragma unroll
                        for (int jj = 0; jj < 2; ++jj) {
                            const int code = cbase + nt * 8 + jj;
                            float d = fmaf(-2.0f, acc[sl >> 1][nt][(sl & 1) * 2 + jj],
                                           __ldg(&g_enorm[code]));
                            if (d < thr) {
                                int ix = atomicAdd(&cnt[rowix[sl]], 1);
                                if (ix < 32) cand[rowix[sl] * 32 + ix] = code;
                            }
                        }
                }
            } else {
#pragma unroll
                for (int sl = 0; sl < 4; ++sl) {
                    float thr = __int_as_float(rowbest[rowix[sl]]) + MARGIN;
                    if (smin[sl] < thr) {   // rare: rescan this slot
#pragma unroll
                        for (int nt = 0; nt < 8; ++nt)
#pragma unroll
                            for (int jj = 0; jj < 2; ++jj) {
                                const int code = cbase + nt * 8 + jj;
                                float d = fmaf(-2.0f, acc[sl >> 1][nt][(sl & 1) * 2 + jj],
                                               __ldg(&g_enorm[code]));
                                if (d < thr) {
                                    int ix = atomicAdd(&cnt[rowix[sl]], 1);
                                    if (ix < 32) cand[rowix[sl] * 32 + ix] = code;
                                }
                            }
                    }
                    atomicMin(&rowbest[rowix[sl]], __float_as_int(smin[sl]));
                }
            }
        }

        cur = (cur == 2) ? 0 : cur + 1;
        nxt = (nxt == 2) ? 0 : nxt + 1;
    }

    __syncthreads();
    // rescore: warp w handles rows w*8 .. w*8+7, exact fp32, index tie-break
    for (int rr = 0; rr < 8; ++rr) {
        const int row = warp * 8 + rr;
        float zreg[8];
#pragma unroll
        for (int i = 0; i < 8; ++i)
            zreg[i] = z[(size_t)(m0 + row) * DIM + i * 32 + lane];
        int nc = cnt[row]; if (nc > 32) nc = 32;
        float bv = 3.4e38f; int bi = 0x7fffffff;
        for (int cix = 0; cix < nc; ++cix) {
            int c = cand[row * 32 + cix];
            const float* ep = &g_embT[(size_t)c * DIM];
            float s = 0.0f;
#pragma unroll
            for (int i = 0; i < 8; ++i)
                s = fmaf(zreg[i], __ldg(&ep[i * 32 + lane]), s);
#pragma unroll
            for (int o = 16; o; o >>= 1) s += __shfl_xor_sync(0xffffffffu, s, o);
            float dist = fmaf(-2.0f, s, __ldg(&g_enorm[c]));
            if (dist < bv || (dist == bv && c < bi)) { bv = dist; bi = c; }
        }
        if (lane == 0) {
            g_argmin[m0 + row] = bi;
            o_ind[m0 + row] = (float)bi;
        }
    }
}

// ================= gather quantize + diff + segment-sum scatter =================
// 4 warps per row (quarter row each) for latency hiding
__global__ void k_scatter(const float* __restrict__ z, float* __restrict__ o_quant,
                          float* __restrict__ o_diff, float* __restrict__ o_cs) {
    int gw = (blockIdx.x * blockDim.x + threadIdx.x) >> 5;
    int lane = threadIdx.x & 31;
    int row = gw >> 2;
    int qt = gw & 3;
    if (row >= NROW) return;
    int j = g_argmin[row];
    int dbase = qt * 64;
    const float* et = &g_embT[(size_t)j * DIM + dbase];
    const float* zr = &z[(size_t)row * DIM + dbase];
    float* qr = &o_quant[(size_t)row * DIM + dbase];
    float* es = &g_esum[(size_t)j * DIM + dbase];
    float s = 0.0f;
#pragma unroll
    for (int it = 0; it < 2; ++it) {
        int d = it * 32 + lane;
        float qv = __ldg(&et[d]);
        float zv = zr[d];
        float dq = qv - zv;
        qr[d] = zv + dq;
        s = fmaf(dq, dq, s);
        atomicAdd(&es[d], zv);
    }
#pragma unroll
    for (int o = 16; o; o >>= 1) s += __shfl_xor_sync(0xffffffffu, s, o);
    if (lane == 0) {
        atomicAdd(o_diff, s * (1.0f / (float)(NROW * DIM)));
        if (qt == 0) atomicAdd(&o_cs[j], OMDF);
    }
}

// ================= n = sum(new_cluster_size) =================
__global__ void k_sumn(const float* __restrict__ o_cs) {
    __shared__ float sh[256];
    float s = 0.0f;
    for (int i = threadIdx.x; i < NEMB; i += 256) s += o_cs[i];
    sh[threadIdx.x] = s;
    __syncthreads();
    for (int o = 128; o; o >>= 1) {
        if (threadIdx.x < o) sh[threadIdx.x] += sh[threadIdx.x + o];
        __syncthreads();
    }
    if (threadIdx.x == 0) g_n = sh[0];
}

// ================= new_embedding_avg + new_embedding =================
__global__ void k_final(const float* __restrict__ avg, const float* __restrict__ o_cs,
                        float* __restrict__ o_emb, float* __restrict__ o_avg) {
    int i = blockIdx.x * blockDim.x + threadIdx.x;
    if (i >= NEMB * DIM) return;
    int d = i >> 13;
    int j = i & (NEMB - 1);
    float na = fmaf(OMDF, g_esum[j * DIM + d], DECAYF * avg[i]);
    o_avg[i] = na;
    float n = g_n;
    float cs = o_cs[j];
    float smth = (cs + EPSF) / (n + (float)NEMB * EPSF) * n;
    o_emb[i] = na / smth;
}

extern "C" void kernel_launch(void* const* d_in, const int* in_sizes, int n_in,
                              void* d_out, int out_size) {
    (void)in_sizes; (void)n_in; (void)out_size;
    const float* z   = (const float*)d_in[0];
    const float* emb = (const float*)d_in[1];
    const float* cs  = (const float*)d_in[2];
    const float* avg = (const float*)d_in[3];

    float* out     = (float*)d_out;
    float* o_quant = out;                 // 4194304
    float* o_diff  = out + 4194304;       // 1
    float* o_ind   = out + 4194305;       // 16384
    float* o_emb   = out + 4210689;       // 2097152
    float* o_cs    = out + 6307841;       // 8192
    float* o_avg   = out + 6316033;       // 2097152

    cudaFuncSetAttribute(k_argmin_mma, cudaFuncAttributeMaxDynamicSharedMemorySize, SMEM_SZ);

    k_prep_z<<<(NROW * DIM + 255) / 256, 256>>>(z);
    {
        dim3 g(NEMB / 32, DIM / 32), b(32, 8);
        k_prep_e<<<g, b>>>(emb);
    }
    k_enorm<<<(NEMB + 255) / 256, 256>>>(emb, cs, o_cs, o_diff);
    k_argmin_mma<<<NROW / 128, 512, SMEM_SZ>>>(z, o_ind);
    k_scatter<<<(NROW * 128) / 256, 256>>>(z, o_quant, o_diff, o_cs);
    k_sumn<<<1, 256>>>(o_cs);
    k_final<<<(NEMB * DIM + 255) / 256, 256>>>(avg, o_cs, o_emb, o_avg);
}

// round 9
// speedup vs baseline: 1.0508x; 1.0508x over previous
#include <cuda_runtime.h>
#include <cuda_fp16.h>
#include <cstdint>

#define DIM    256
#define NEMB   8192
#define NROW   16384
#define DECAYF 0.99f
#define OMDF   0.01f
#define EPSF   1e-5f
#define MARGIN 1.0f

// A: 128 rows x 512B (256 fp16), padded stride 528B
#define AST    528
#define AREG   (128 * AST)          // 67584
#define BST    272                  // B stage row: 128 fp16 = 256B + 16 pad
#define BBUF   (256 * BST)          // 69632 (256 codes x 128 k per stage)
#define SM_A   0
#define SM_B   AREG                 // 67584
#define SM_RB  (SM_B + 2 * BBUF)    // 206848 rowbest int[128]
#define SM_CNT (SM_RB + 512)        // 207360 cnt int[128]
#define SM_CD  (SM_CNT + 512)       // 207872 cand int[128*32]
#define SMEM_SZ (SM_CD + 128 * 32 * 4)  // 224256
#define NSTG   64                   // 32 chunks (256 codes) x 2 k-stages

// ---- scratch (device globals: no allocations allowed) ----
__device__ float g_enorm[NEMB];
__device__ float g_embT[NEMB * DIM];          // [j][d] fp32 for rescore + gather
__device__ float g_esum[NEMB * DIM];          // [j][d] segment sums
__device__ int   g_argmin[NROW];
__device__ float g_n;
__device__ __half g_zsH[(size_t)NROW * DIM];  // [m][d] fp16
__device__ __half g_esH[(size_t)NEMB * DIM];  // [j][d] fp16

// ================= helpers =================
__device__ __forceinline__ uint32_t smem_u32(const void* p) {
    uint32_t a;
    asm("{ .reg .u64 t; cvta.to.shared.u64 t, %1; cvt.u32.u64 %0, t; }" : "=r"(a) : "l"(p));
    return a;
}
__device__ __forceinline__ void cpa16(uint32_t dst, const void* src) {
    asm volatile("cp.async.cg.shared.global [%0], [%1], 16;" :: "r"(dst), "l"(src));
}
__device__ __forceinline__ void ldm4(uint32_t (&r)[4], uint32_t addr) {
    asm volatile("ldmatrix.sync.aligned.m8n8.x4.shared.b16 {%0,%1,%2,%3}, [%4];"
                 : "=r"(r[0]), "=r"(r[1]), "=r"(r[2]), "=r"(r[3]) : "r"(addr));
}
__device__ __forceinline__ void mma16816(float (&d)[4], const uint32_t (&a)[4],
                                         uint32_t b0, uint32_t b1) {
    asm volatile(
        "mma.sync.aligned.m16n8k16.row.col.f32.f16.f16.f32 "
        "{%0,%1,%2,%3},{%4,%5,%6,%7},{%8,%9},{%0,%1,%2,%3};"
        : "+f"(d[0]), "+f"(d[1]), "+f"(d[2]), "+f"(d[3])
        : "r"(a[0]), "r"(a[1]), "r"(a[2]), "r"(a[3]), "r"(b0), "r"(b1));
}

// ================= prep: z -> fp16 =================
__global__ void k_prep_z(const float* __restrict__ z) {
    int i = blockIdx.x * blockDim.x + threadIdx.x;
    if (i < NROW * DIM) g_zsH[i] = __float2half(z[i]);
}

// ================= prep: emb -> fp16 + embT + esum=0 (tiled transpose) ====
__global__ void k_prep_e(const float* __restrict__ emb) {
    __shared__ float t[32][33];
    int j0 = blockIdx.x * 32, d0 = blockIdx.y * 32;
    for (int r = threadIdx.y; r < 32; r += 8)
        t[r][threadIdx.x] = emb[(size_t)(d0 + r) * NEMB + j0 + threadIdx.x];
    __syncthreads();
    for (int r = threadIdx.y; r < 32; r += 8) {
        int j = j0 + r, d = d0 + threadIdx.x;
        float x = t[threadIdx.x][r];
        g_esH[(size_t)j * DIM + d] = __float2half(x);
        g_embT[j * DIM + d] = x;
        g_esum[j * DIM + d] = 0.0f;
    }
}

// ================= code norms + init cs + zero diff =================
__global__ void k_enorm(const float* __restrict__ emb, const float* __restrict__ cs,
                        float* __restrict__ o_cs, float* __restrict__ o_diff) {
    int j = blockIdx.x * blockDim.x + threadIdx.x;
    if (j < NEMB) {
        float s = 0.0f;
#pragma unroll 8
        for (int d = 0; d < DIM; ++d) {
            float v = emb[(size_t)d * NEMB + j];
            s = fmaf(v, v, s);
        }
        g_enorm[j] = s;
        o_cs[j] = DECAYF * cs[j];
        if (j == 0) *o_diff = 0.0f;
    }
}

// ================= main: fp16 approx GEMM + threshold candidates + rescore ======
__device__ __forceinline__ void load_B(int t, int slot, int tid, uint32_t sb) {
    const int n0 = (t >> 1) << 8;       // chunk * 256 codes
    const int scol = (t & 1) << 7;      // k-half * 128
    const char* ea = (const char*)g_esH;
#pragma unroll
    for (int r = 0; r < 8; ++r) {
        int i = tid + (r << 9);
        int c = i & 15, row = i >> 4;   // 256 rows x 16 chunks of 16B
        cpa16(sb + SM_B + slot * BBUF + row * BST + c * 16,
              ea + (((size_t)(n0 + row) << 8) + scol) * 2 + c * 16);
    }
}

__global__ __launch_bounds__(512, 1)
void k_argmin_mma(const float* __restrict__ z, float* __restrict__ o_ind) {
    extern __shared__ char smm[];
    uint32_t sb = smem_u32(smm);
    const int tid = threadIdx.x;
    const int lane = tid & 31;
    const int warp = tid >> 5;
    const int warpM = warp >> 2;        // 0..3 (32 rows each)
    const int warpN = warp & 3;         // 0..3 (64 codes each)
    const int m0 = blockIdx.x * 128;

    int* rowbest = (int*)(smm + SM_RB);
    int* cnt     = (int*)(smm + SM_CNT);
    int* cand    = (int*)(smm + SM_CD);
    if (tid < 128) { rowbest[tid] = 0x7f800000; cnt[tid] = 0; }

    // per-lane ldmatrix offsets
    const int q = lane >> 3, rq = lane & 7;
    const int lrow = (q & 1) * 8 + rq;
    const int lbyte = (q >> 1) * 16;
    const uint32_t a_lane = (uint32_t)lrow * AST + lbyte;
    const uint32_t b_lane = (uint32_t)lrow * BST + lbyte;

    // prologue: A + stage0
    const char* za = (const char*)g_zsH;
#pragma unroll
    for (int r = 0; r < 8; ++r) {
        int i = tid + (r << 9);
        int c = i & 31, row = i >> 5;
        cpa16(sb + SM_A + row * AST + c * 16,
              za + ((size_t)(m0 + row) << 8) * 2 + c * 16);
    }
    load_B(0, 0, tid, sb);
    asm volatile("cp.async.commit_group;" ::: "memory");

    const int lq = lane >> 2;
    const int ln = (lane & 3) * 2;
    int rowix[4];
#pragma unroll
    for (int sl = 0; sl < 4; ++sl)
        rowix[sl] = warpM * 32 + (sl >> 1) * 16 + (sl & 1) * 8 + lq;

    float acc[2][8][4];

    for (int t = 0; t < NSTG; ++t) {
        const int cur = t & 1;
        if (cur == 0) {
#pragma unroll
            for (int mt = 0; mt < 2; ++mt)
#pragma unroll
                for (int nt = 0; nt < 8; ++nt)
#pragma unroll
                    for (int x = 0; x < 4; ++x) acc[mt][nt][x] = 0.0f;
        }

        asm volatile("cp.async.wait_group 0;" ::: "memory");
        __syncthreads();       // slot cur ready; previous compute done

        if (t + 1 < NSTG) {
            load_B(t + 1, cur ^ 1, tid, sb);
            asm volatile("cp.async.commit_group;" ::: "memory");
        }

        const uint32_t Bb = sb + SM_B + cur * BBUF + (warpN * 64) * BST + b_lane;
        const uint32_t Ab0 = sb + SM_A + (warpM * 32) * AST + cur * 256 + a_lane;
#pragma unroll
        for (int kk = 0; kk < 8; ++kk) {
            uint32_t b[4][4];
#pragma unroll
            for (int g = 0; g < 4; ++g)
                ldm4(b[g], Bb + g * 16 * BST + kk * 32);
            uint32_t a0[4], a1[4];
            ldm4(a0, Ab0 + kk * 32);
            ldm4(a1, Ab0 + 16 * AST + kk * 32);
#pragma unroll
            for (int nt = 0; nt < 8; ++nt) {
                uint32_t bb0 = b[nt >> 1][nt & 1];
                uint32_t bb1 = b[nt >> 1][(nt & 1) + 2];
                mma16816(acc[0][nt], a0, bb0, bb1);
                mma16816(acc[1][nt], a1, bb0, bb1);
            }
        }

        if (cur == 1) {   // chunk done
            const int cbase = ((t >> 1) << 8) + warpN * 64 + ln;
            float smin[4] = {3.4e38f, 3.4e38f, 3.4e38f, 3.4e38f};
#pragma unroll
            for (int nt = 0; nt < 8; ++nt) {
#pragma unroll
                for (int jj = 0; jj < 2; ++jj) {
                    const float en = __ldg(&g_enorm[cbase + nt * 8 + jj]);
#pragma unroll
                    for (int mt = 0; mt < 2; ++mt)
#pragma unroll
                        for (int h = 0; h < 2; ++h) {
                            float d = fmaf(-2.0f, acc[mt][nt][h * 2 + jj], en);
                            smin[mt * 2 + h] = fminf(smin[mt * 2 + h], d);
                        }
                }
            }
            if (t == 1) {
                // seed rowbest from chunk 0, then append chunk-0 candidates
#pragma unroll
                for (int sl = 0; sl < 4; ++sl)
                    atomicMin(&rowbest[rowix[sl]], __float_as_int(smin[sl]));
                __syncthreads();
#pragma unroll
                for (int sl = 0; sl < 4; ++sl) {
                    float thr = __int_as_float(rowbest[rowix[sl]]) + MARGIN;
#pragma unroll
                    for (int nt = 0; nt < 8; ++nt)
#pragma unroll
                        for (int jj = 0; jj < 2; ++jj) {
                            const int code = cbase + nt * 8 + jj;
                            float d = fmaf(-2.0f, acc[sl >> 1][nt][(sl & 1) * 2 + jj],
                                           __ldg(&g_enorm[code]));
                            if (d < thr) {
                                int ix = atomicAdd(&cnt[rowix[sl]], 1);
                                if (ix < 32) cand[rowix[sl] * 32 + ix] = code;
                            }
                        }
                }
            } else {
#pragma unroll
                for (int sl = 0; sl < 4; ++sl) {
                    float thr = __int_as_float(rowbest[rowix[sl]]) + MARGIN;
                    if (smin[sl] < thr) {   // rare: rescan this slot
#pragma unroll
                        for (int nt = 0; nt < 8; ++nt)
#pragma unroll
                            for (int jj = 0; jj < 2; ++jj) {
                                const int code = cbase + nt * 8 + jj;
                                float d = fmaf(-2.0f, acc[sl >> 1][nt][(sl & 1) * 2 + jj],
                                               __ldg(&g_enorm[code]));
                                if (d < thr) {
                                    int ix = atomicAdd(&cnt[rowix[sl]], 1);
                                    if (ix < 32) cand[rowix[sl] * 32 + ix] = code;
                                }
                            }
                    }
                    atomicMin(&rowbest[rowix[sl]], __float_as_int(smin[sl]));
                }
            }
        }
    }

    __syncthreads();
    // rescore: warp w handles rows w*8 .. w*8+7, exact fp32, index tie-break
    for (int rr = 0; rr < 8; ++rr) {
        const int row = warp * 8 + rr;
        float zreg[8];
#pragma unroll
        for (int i = 0; i < 8; ++i)
            zreg[i] = z[(size_t)(m0 + row) * DIM + i * 32 + lane];
        int nc = cnt[row]; if (nc > 32) nc = 32;
        float bv = 3.4e38f; int bi = 0x7fffffff;
        for (int cix = 0; cix < nc; ++cix) {
            int c = cand[row * 32 + cix];
            const float* ep = &g_embT[(size_t)c * DIM];
            float s = 0.0f;
#pragma unroll
            for (int i = 0; i < 8; ++i)
                s = fmaf(zreg[i], __ldg(&ep[i * 32 + lane]), s);
#pragma unroll
            for (int o = 16; o; o >>= 1) s += __shfl_xor_sync(0xffffffffu, s, o);
            float dist = fmaf(-2.0f, s, __ldg(&g_enorm[c]));
            if (dist < bv || (dist == bv && c < bi)) { bv = dist; bi = c; }
        }
        if (lane == 0) {
            g_argmin[m0 + row] = bi;
            o_ind[m0 + row] = (float)bi;
        }
    }
}

// ================= gather quantize + diff + segment-sum scatter =================
// 2 warps per row; block-level diff accumulation (1 global atomic per block)
__global__ void k_scatter(const float* __restrict__ z, float* __restrict__ o_quant,
                          float* __restrict__ o_diff, float* __restrict__ o_cs) {
    __shared__ float sdiff;
    if (threadIdx.x == 0) sdiff = 0.0f;
    __syncthreads();
    int gw = (blockIdx.x * blockDim.x + threadIdx.x) >> 5;
    int lane = threadIdx.x & 31;
    int row = gw >> 1;
    int half = gw & 1;
    float s = 0.0f;
    int j = -1;
    if (row < NROW) {
        j = g_argmin[row];
        int dbase = half * 128;
        const float* et = &g_embT[(size_t)j * DIM + dbase];
        const float* zr = &z[(size_t)row * DIM + dbase];
        float* qr = &o_quant[(size_t)row * DIM + dbase];
        float* es = &g_esum[(size_t)j * DIM + dbase];
#pragma unroll
        for (int it = 0; it < 4; ++it) {
            int d = it * 32 + lane;
            float qv = __ldg(&et[d]);
            float zv = zr[d];
            float dq = qv - zv;
            qr[d] = zv + dq;
            s = fmaf(dq, dq, s);
            atomicAdd(&es[d], zv);
        }
    }
#pragma unroll
    for (int o = 16; o; o >>= 1) s += __shfl_xor_sync(0xffffffffu, s, o);
    if (lane == 0 && row < NROW) {
        atomicAdd(&sdiff, s);
        if (half == 0) atomicAdd(&o_cs[j], OMDF);
    }
    __syncthreads();
    if (threadIdx.x == 0)
        atomicAdd(o_diff, sdiff * (1.0f / (float)(NROW * DIM)));
}

// ================= n = sum(new_cluster_size) =================
__global__ void k_sumn(const float* __restrict__ o_cs) {
    __shared__ float sh[256];
    float s = 0.0f;
    for (int i = threadIdx.x; i < NEMB; i += 256) s += o_cs[i];
    sh[threadIdx.x] = s;
    __syncthreads();
    for (int o = 128; o; o >>= 1) {
        if (threadIdx.x < o) sh[threadIdx.x] += sh[threadIdx.x + o];
        __syncthreads();
    }
    if (threadIdx.x == 0) g_n = sh[0];
}

// ================= new_embedding_avg + new_embedding =================
__global__ void k_final(const float* __restrict__ avg, const float* __restrict__ o_cs,
                        float* __restrict__ o_emb, float* __restrict__ o_avg) {
    int i = blockIdx.x * blockDim.x + threadIdx.x;
    if (i >= NEMB * DIM) return;
    int d = i >> 13;
    int j = i & (NEMB - 1);
    float na = fmaf(OMDF, g_esum[j * DIM + d], DECAYF * avg[i]);
    o_avg[i] = na;
    float n = g_n;
    float cs = o_cs[j];
    float smth = (cs + EPSF) / (n + (float)NEMB * EPSF) * n;
    o_emb[i] = na / smth;
}

extern "C" void kernel_launch(void* const* d_in, const int* in_sizes, int n_in,
                              void* d_out, int out_size) {
    (void)in_sizes; (void)n_in; (void)out_size;
    const float* z   = (const float*)d_in[0];
    const float* emb = (const float*)d_in[1];
    const float* cs  = (const float*)d_in[2];
    const float* avg = (const float*)d_in[3];

    float* out     = (float*)d_out;
    float* o_quant = out;                 // 4194304
    float* o_diff  = out + 4194304;       // 1
    float* o_ind   = out + 4194305;       // 16384
    float* o_emb   = out + 4210689;       // 2097152
    float* o_cs    = out + 6307841;       // 8192
    float* o_avg   = out + 6316033;       // 2097152

    cudaFuncSetAttribute(k_argmin_mma, cudaFuncAttributeMaxDynamicSharedMemorySize, SMEM_SZ);

    k_prep_z<<<(NROW * DIM + 255) / 256, 256>>>(z);
    {
        dim3 g(NEMB / 32, DIM / 32), b(32, 8);
        k_prep_e<<<g, b>>>(emb);
    }
    k_enorm<<<(NEMB + 255) / 256, 256>>>(emb, cs, o_cs, o_diff);
    k_argmin_mma<<<NROW / 128, 512, SMEM_SZ>>>(z, o_ind);
    k_scatter<<<(NROW * 64) / 256, 256>>>(z, o_quant, o_diff, o_cs);
    k_sumn<<<1, 256>>>(o_cs);
    k_final<<<(NEMB * DIM + 255) / 256, 256>>>(avg, o_cs, o_emb, o_avg);
}

// round 10
// speedup vs baseline: 1.2582x; 1.1974x over previous
#include <cuda_runtime.h>
#include <cuda_fp16.h>
#include <cstdint>

#define DIM    256
#define NEMB   8192
#define NROW   16384
#define DECAYF 0.99f
#define OMDF   0.01f
#define EPSF   1e-5f
#define MARGIN 1.0f

// A: 128 rows x 512B (256 fp16), padded stride 528B
#define AST    528
#define AREG   (128 * AST)          // 67584
#define BST    144                  // B slice row: 64 fp16 = 128B + 16 pad
#define BBUF   (256 * BST)          // 36864 (256 codes per stage)
#define SM_A   0
#define SM_B   AREG                 // 67584
#define SM_RB  (SM_B + 3 * BBUF)    // 178176 rowbest int[128]
#define SM_CNT (SM_RB + 512)        // cnt int[128]
#define SM_CD  (SM_CNT + 512)       // cand int[128*32]
#define SMEM_SZ (SM_CD + 128 * 32 * 4)  // 195584
#define NSTG   128                  // 32 chunks (256 codes) x 4 k-stages

// ---- scratch (device globals: no allocations allowed) ----
__device__ float g_enorm[NEMB];
__device__ float g_embT[NEMB * DIM];          // [j][d] fp32 for rescore + gather
__device__ float g_esum[NEMB * DIM];          // [j][d] segment sums
__device__ int   g_argmin[NROW];
__device__ float g_n;
__device__ __half g_zsH[(size_t)NROW * DIM];  // [m][d] fp16
__device__ __half g_esH[(size_t)NEMB * DIM];  // [j][d] fp16

// ================= helpers =================
__device__ __forceinline__ uint32_t smem_u32(const void* p) {
    uint32_t a;
    asm("{ .reg .u64 t; cvta.to.shared.u64 t, %1; cvt.u32.u64 %0, t; }" : "=r"(a) : "l"(p));
    return a;
}
__device__ __forceinline__ void cpa16(uint32_t dst, const void* src) {
    asm volatile("cp.async.cg.shared.global [%0], [%1], 16;" :: "r"(dst), "l"(src));
}
__device__ __forceinline__ void ldm4(uint32_t (&r)[4], uint32_t addr) {
    asm volatile("ldmatrix.sync.aligned.m8n8.x4.shared.b16 {%0,%1,%2,%3}, [%4];"
                 : "=r"(r[0]), "=r"(r[1]), "=r"(r[2]), "=r"(r[3]) : "r"(addr));
}
__device__ __forceinline__ void mma16816(float (&d)[4], const uint32_t (&a)[4],
                                         uint32_t b0, uint32_t b1) {
    asm volatile(
        "mma.sync.aligned.m16n8k16.row.col.f32.f16.f16.f32 "
        "{%0,%1,%2,%3},{%4,%5,%6,%7},{%8,%9},{%0,%1,%2,%3};"
        : "+f"(d[0]), "+f"(d[1]), "+f"(d[2]), "+f"(d[3])
        : "r"(a[0]), "r"(a[1]), "r"(a[2]), "r"(a[3]), "r"(b0), "r"(b1));
}

// ================= prep: z -> fp16 =================
__global__ void k_prep_z(const float* __restrict__ z) {
    int i = blockIdx.x * blockDim.x + threadIdx.x;
    if (i < NROW * DIM) g_zsH[i] = __float2half(z[i]);
}

// ================= prep: emb -> fp16 + embT + esum=0 (tiled transpose) ====
__global__ void k_prep_e(const float* __restrict__ emb) {
    __shared__ float t[32][33];
    int j0 = blockIdx.x * 32, d0 = blockIdx.y * 32;
    for (int r = threadIdx.y; r < 32; r += 8)
        t[r][threadIdx.x] = emb[(size_t)(d0 + r) * NEMB + j0 + threadIdx.x];
    __syncthreads();
    for (int r = threadIdx.y; r < 32; r += 8) {
        int j = j0 + r, d = d0 + threadIdx.x;
        float x = t[threadIdx.x][r];
        g_esH[(size_t)j * DIM + d] = __float2half(x);
        g_embT[j * DIM + d] = x;
        g_esum[j * DIM + d] = 0.0f;
    }
}

// ================= code norms + init cs + zero diff =================
__global__ void k_enorm(const float* __restrict__ emb, const float* __restrict__ cs,
                        float* __restrict__ o_cs, float* __restrict__ o_diff) {
    int j = blockIdx.x * blockDim.x + threadIdx.x;
    if (j < NEMB) {
        float s = 0.0f;
#pragma unroll 8
        for (int d = 0; d < DIM; ++d) {
            float v = emb[(size_t)d * NEMB + j];
            s = fmaf(v, v, s);
        }
        g_enorm[j] = s;
        o_cs[j] = DECAYF * cs[j];
        if (j == 0) *o_diff = 0.0f;
    }
}

// ================= main: fp16 approx GEMM + threshold candidates + rescore ======
__device__ __forceinline__ void load_B(int t, int slot, int tid, uint32_t sb) {
    const int n0 = (t >> 2) << 8;       // chunk * 256 codes
    const int scol = (t & 3) << 6;      // k-slice * 64
    const char* ea = (const char*)g_esH;
#pragma unroll
    for (int r = 0; r < 4; ++r) {
        int i = tid + (r << 9);
        int c = i & 7, row = i >> 3;    // 256 rows x 8 chunks of 16B
        cpa16(sb + SM_B + slot * BBUF + row * BST + c * 16,
              ea + (((size_t)(n0 + row) << 8) + scol) * 2 + c * 16);
    }
}

__global__ __launch_bounds__(512, 1)
void k_argmin_mma(const float* __restrict__ z, float* __restrict__ o_ind) {
    extern __shared__ char smm[];
    uint32_t sb = smem_u32(smm);
    const int tid = threadIdx.x;
    const int lane = tid & 31;
    const int warp = tid >> 5;
    const int warpM = warp >> 2;        // 0..3 (32 rows each)
    const int warpN = warp & 3;         // 0..3 (64 codes each)
    const int m0 = blockIdx.x * 128;

    int* rowbest = (int*)(smm + SM_RB);
    int* cnt     = (int*)(smm + SM_CNT);
    int* cand    = (int*)(smm + SM_CD);
    if (tid < 128) { rowbest[tid] = 0x7f800000; cnt[tid] = 0; }

    // per-lane ldmatrix offsets
    const int q = lane >> 3, rq = lane & 7;
    const int lrow = (q & 1) * 8 + rq;
    const int lbyte = (q >> 1) * 16;
    const uint32_t a_lane = (uint32_t)lrow * AST + lbyte;
    const uint32_t b_lane = (uint32_t)lrow * BST + lbyte;

    // prologue: A + stage0 -> group0; stage1 -> group1
    const char* za = (const char*)g_zsH;
#pragma unroll
    for (int r = 0; r < 8; ++r) {
        int i = tid + (r << 9);
        int c = i & 31, row = i >> 5;
        cpa16(sb + SM_A + row * AST + c * 16,
              za + ((size_t)(m0 + row) << 8) * 2 + c * 16);
    }
    load_B(0, 0, tid, sb);
    asm volatile("cp.async.commit_group;" ::: "memory");
    load_B(1, 1, tid, sb);
    asm volatile("cp.async.commit_group;" ::: "memory");

    const int lq = lane >> 2;
    const int ln = (lane & 3) * 2;
    int rowix[4];
#pragma unroll
    for (int sl = 0; sl < 4; ++sl)
        rowix[sl] = warpM * 32 + (sl >> 1) * 16 + (sl & 1) * 8 + lq;

    float acc[2][8][4];
    int cur = 0, nxt = 2;

    for (int t = 0; t < NSTG; ++t) {
        const int s = t & 3;
        if (s == 0) {
#pragma unroll
            for (int mt = 0; mt < 2; ++mt)
#pragma unroll
                for (int nt = 0; nt < 8; ++nt)
#pragma unroll
                    for (int x = 0; x < 4; ++x) acc[mt][nt][x] = 0.0f;
        }

        if (t == NSTG - 1) {
            asm volatile("cp.async.wait_group 0;" ::: "memory");
        } else {
            asm volatile("cp.async.wait_group 1;" ::: "memory");
        }
        __syncthreads();

        if (t + 2 < NSTG) {
            load_B(t + 2, nxt, tid, sb);
            asm volatile("cp.async.commit_group;" ::: "memory");
        }

        const uint32_t Bb = sb + SM_B + cur * BBUF + (warpN * 64) * BST + b_lane;
        const uint32_t Ab0 = sb + SM_A + (warpM * 32) * AST + s * 128 + a_lane;
#pragma unroll
        for (int kk = 0; kk < 4; ++kk) {
            uint32_t b[4][4];
#pragma unroll
            for (int g = 0; g < 4; ++g)
                ldm4(b[g], Bb + g * 16 * BST + kk * 32);
            uint32_t a0[4], a1[4];
            ldm4(a0, Ab0 + kk * 32);
            ldm4(a1, Ab0 + 16 * AST + kk * 32);
#pragma unroll
            for (int nt = 0; nt < 8; ++nt) {
                uint32_t bb0 = b[nt >> 1][nt & 1];
                uint32_t bb1 = b[nt >> 1][(nt & 1) + 2];
                mma16816(acc[0][nt], a0, bb0, bb1);
                mma16816(acc[1][nt], a1, bb0, bb1);
            }
        }

        if (s == 3) {   // chunk done
            const int n0 = (t >> 2) << 8;
            const int cbase = n0 + warpN * 64 + ln;
            float smin[4] = {3.4e38f, 3.4e38f, 3.4e38f, 3.4e38f};
#pragma unroll
            for (int nt = 0; nt < 8; ++nt) {
#pragma unroll
                for (int jj = 0; jj < 2; ++jj) {
                    const float en = __ldg(&g_enorm[cbase + nt * 8 + jj]);
#pragma unroll
                    for (int mt = 0; mt < 2; ++mt)
#pragma unroll
                        for (int h = 0; h < 2; ++h) {
                            float d = fmaf(-2.0f, acc[mt][nt][h * 2 + jj], en);
                            smin[mt * 2 + h] = fminf(smin[mt * 2 + h], d);
                        }
                }
            }
            if (t == 3) {
                // seed rowbest from chunk 0, then append chunk-0 candidates
#pragma unroll
                for (int sl = 0; sl < 4; ++sl)
                    atomicMin(&rowbest[rowix[sl]], __float_as_int(smin[sl]));
                __syncthreads();
#pragma unroll
                for (int sl = 0; sl < 4; ++sl) {
                    float thr = __int_as_float(rowbest[rowix[sl]]) + MARGIN;
#pragma unroll
                    for (int nt = 0; nt < 8; ++nt)
#pragma unroll
                        for (int jj = 0; jj < 2; ++jj) {
                            const int code = cbase + nt * 8 + jj;
                            float d = fmaf(-2.0f, acc[sl >> 1][nt][(sl & 1) * 2 + jj],
                                           __ldg(&g_enorm[code]));
                            if (d < thr) {
                                int ix = atomicAdd(&cnt[rowix[sl]], 1);
                                if (ix < 32) cand[rowix[sl] * 32 + ix] = code;
                            }
                        }
                }
            } else {
#pragma unroll
                for (int sl = 0; sl < 4; ++sl) {
                    float thr = __int_as_float(rowbest[rowix[sl]]) + MARGIN;
                    if (smin[sl] < thr) {   // rare: rescan this slot
#pragma unroll
                        for (int nt = 0; nt < 8; ++nt)
#pragma unroll
                            for (int jj = 0; jj < 2; ++jj) {
                                const int code = cbase + nt * 8 + jj;
                                float d = fmaf(-2.0f, acc[sl >> 1][nt][(sl & 1) * 2 + jj],
                                               __ldg(&g_enorm[code]));
                                if (d < thr) {
                                    int ix = atomicAdd(&cnt[rowix[sl]], 1);
                                    if (ix < 32) cand[rowix[sl] * 32 + ix] = code;
                                }
                            }
                    }
                    atomicMin(&rowbest[rowix[sl]], __float_as_int(smin[sl]));
                }
            }
        }

        cur = (cur == 2) ? 0 : cur + 1;
        nxt = (nxt == 2) ? 0 : nxt + 1;
    }

    __syncthreads();
    // rescore: warp w handles rows w*8 .. w*8+7, exact fp32, index tie-break
    for (int rr = 0; rr < 8; ++rr) {
        const int row = warp * 8 + rr;
        float zreg[8];
#pragma unroll
        for (int i = 0; i < 8; ++i)
            zreg[i] = z[(size_t)(m0 + row) * DIM + i * 32 + lane];
        int nc = cnt[row]; if (nc > 32) nc = 32;
        float bv = 3.4e38f; int bi = 0x7fffffff;
        for (int cix = 0; cix < nc; ++cix) {
            int c = cand[row * 32 + cix];
            const float* ep = &g_embT[(size_t)c * DIM];
            float s = 0.0f;
#pragma unroll
            for (int i = 0; i < 8; ++i)
                s = fmaf(zreg[i], __ldg(&ep[i * 32 + lane]), s);
#pragma unroll
            for (int o = 16; o; o >>= 1) s += __shfl_xor_sync(0xffffffffu, s, o);
            float dist = fmaf(-2.0f, s, __ldg(&g_enorm[c]));
            if (dist < bv || (dist == bv && c < bi)) { bv = dist; bi = c; }
        }
        if (lane == 0) {
            g_argmin[m0 + row] = bi;
            o_ind[m0 + row] = (float)bi;
        }
    }
}

// ================= gather quantize + diff + segment-sum scatter =================
// 2 warps per row; block-level diff accumulation (1 global atomic per block)
__global__ void k_scatter(const float* __restrict__ z, float* __restrict__ o_quant,
                          float* __restrict__ o_diff, float* __restrict__ o_cs) {
    __shared__ float sdiff;
    if (threadIdx.x == 0) sdiff = 0.0f;
    __syncthreads();
    int gw = (blockIdx.x * blockDim.x + threadIdx.x) >> 5;
    int lane = threadIdx.x & 31;
    int row = gw >> 1;
    int half = gw & 1;
    float s = 0.0f;
    int j = -1;
    if (row < NROW) {
        j = g_argmin[row];
        int dbase = half * 128;
        const float* et = &g_embT[(size_t)j * DIM + dbase];
        const float* zr = &z[(size_t)row * DIM + dbase];
        float* qr = &o_quant[(size_t)row * DIM + dbase];
        float* es = &g_esum[(size_t)j * DIM + dbase];
#pragma unroll
        for (int it = 0; it < 4; ++it) {
            int d = it * 32 + lane;
            float qv = __ldg(&et[d]);
            float zv = zr[d];
            float dq = qv - zv;
            qr[d] = zv + dq;
            s = fmaf(dq, dq, s);
            atomicAdd(&es[d], zv);
        }
    }
#pragma unroll
    for (int o = 16; o; o >>= 1) s += __shfl_xor_sync(0xffffffffu, s, o);
    if (lane == 0 && row < NROW) {
        atomicAdd(&sdiff, s);
        if (half == 0) atomicAdd(&o_cs[j], OMDF);
    }
    __syncthreads();
    if (threadIdx.x == 0)
        atomicAdd(o_diff, sdiff * (1.0f / (float)(NROW * DIM)));
}

// ================= n = sum(new_cluster_size) =================
__global__ void k_sumn(const float* __restrict__ o_cs) {
    __shared__ float sh[256];
    float s = 0.0f;
    for (int i = threadIdx.x; i < NEMB; i += 256) s += o_cs[i];
    sh[threadIdx.x] = s;
    __syncthreads();
    for (int o = 128; o; o >>= 1) {
        if (threadIdx.x < o) sh[threadIdx.x] += sh[threadIdx.x + o];
        __syncthreads();
    }
    if (threadIdx.x == 0) g_n = sh[0];
}

// ================= new_embedding_avg + new_embedding =================
__global__ void k_final(const float* __restrict__ avg, const float* __restrict__ o_cs,
                        float* __restrict__ o_emb, float* __restrict__ o_avg) {
    int i = blockIdx.x * blockDim.x + threadIdx.x;
    if (i >= NEMB * DIM) return;
    int d = i >> 13;
    int j = i & (NEMB - 1);
    float na = fmaf(OMDF, g_esum[j * DIM + d], DECAYF * avg[i]);
    o_avg[i] = na;
    float n = g_n;
    float cs = o_cs[j];
    float smth = (cs + EPSF) / (n + (float)NEMB * EPSF) * n;
    o_emb[i] = na / smth;
}

extern "C" void kernel_launch(void* const* d_in, const int* in_sizes, int n_in,
                              void* d_out, int out_size) {
    (void)in_sizes; (void)n_in; (void)out_size;
    const float* z   = (const float*)d_in[0];
    const float* emb = (const float*)d_in[1];
    const float* cs  = (const float*)d_in[2];
    const float* avg = (const float*)d_in[3];

    float* out     = (float*)d_out;
    float* o_quant = out;                 // 4194304
    float* o_diff  = out + 4194304;       // 1
    float* o_ind   = out + 4194305;       // 16384
    float* o_emb   = out + 4210689;       // 2097152
    float* o_cs    = out + 6307841;       // 8192
    float* o_avg   = out + 6316033;       // 2097152

    cudaFuncSetAttribute(k_argmin_mma, cudaFuncAttributeMaxDynamicSharedMemorySize, SMEM_SZ);

    k_prep_z<<<(NROW * DIM + 255) / 256, 256>>>(z);
    {
        dim3 g(NEMB / 32, DIM / 32), b(32, 8);
        k_prep_e<<<g, b>>>(emb);
    }
    k_enorm<<<(NEMB + 255) / 256, 256>>>(emb, cs, o_cs, o_diff);
    k_argmin_mma<<<NROW / 128, 512, SMEM_SZ>>>(z, o_ind);
    k_scatter<<<(NROW * 64) / 256, 256>>>(z, o_quant, o_diff, o_cs);
    k_sumn<<<1, 256>>>(o_cs);
    k_final<<<(NEMB * DIM + 255) / 256, 256>>>(avg, o_cs, o_emb, o_avg);
}